// round 6
// baseline (speedup 1.0000x reference)
#include <cuda_runtime.h>
#include <cuda_fp16.h>
#include <math.h>
#include <stdint.h>

// Problem constants
#define BATCH_M   16384   // B*S
#define DIM_D     768
#define DIM_N     2304    // 3*D
#define NUM_T     10
#define RANK_R    16
#define SEG       (RANK_R * DIM_D)

// GEMM tiling: CTA 128x256, 8 warps, warp tile 64x64
#define BM 128
#define BN 256
#define BK 32                      // fp16 elems per K stage
#define KSTAGES (DIM_D / BK)       // 24

// SMEM: rows padded to 80B (conflict-free ldmatrix)
#define ROWB     80
#define A_BYTES  (BM * ROWB)       // 10240
#define B_BYTES  (BN * ROWB)       // 20480
#define STAGEB   (A_BYTES + B_BYTES)   // 30720
#define NSTAGE   4
#define SMEM_TOTAL (NSTAGE * STAGEB)   // 122880

// Device scratch (no cudaMalloc allowed)
__device__ float g_sumsq[40];
__device__ float g_wq[NUM_T];
__device__ float g_wv[NUM_T];
__device__ __align__(16) unsigned short g_Xh[(size_t)BATCH_M * DIM_D];
__device__ __align__(16) unsigned short g_Wh[(size_t)DIM_N * DIM_D];

// ---------------------------------------------------------------------------
// Helpers
// ---------------------------------------------------------------------------
__device__ __forceinline__ uint32_t smem_u32(const void* p) {
    uint32_t a;
    asm("{ .reg .u64 t; cvta.to.shared.u64 t, %1; cvt.u32.u64 %0, t; }" : "=r"(a) : "l"(p));
    return a;
}
#define CP16(dst, src) \
    asm volatile("cp.async.cg.shared.global [%0], [%1], 16;" :: "r"(dst), "l"(src))
#define CP_COMMIT() asm volatile("cp.async.commit_group;" ::: "memory")
#define CP_WAIT2()  asm volatile("cp.async.wait_group 2;"  ::: "memory")

__device__ __forceinline__ void ldsm_x4(uint32_t* r, uint32_t addr) {
    asm volatile("ldmatrix.sync.aligned.m8n8.x4.shared.b16 {%0,%1,%2,%3}, [%4];"
        : "=r"(r[0]), "=r"(r[1]), "=r"(r[2]), "=r"(r[3]) : "r"(addr));
}
__device__ __forceinline__ void mma_fp16(float* c, const uint32_t* a,
                                         uint32_t b0, uint32_t b1) {
    asm volatile("mma.sync.aligned.m16n8k16.row.col.f32.f16.f16.f32 "
        "{%0,%1,%2,%3},{%4,%5,%6,%7},{%8,%9},{%0,%1,%2,%3};"
        : "+f"(c[0]), "+f"(c[1]), "+f"(c[2]), "+f"(c[3])
        : "r"(a[0]), "r"(a[1]), "r"(a[2]), "r"(a[3]), "r"(b0), "r"(b1));
}

// ---------------------------------------------------------------------------
// Kernel 1: per-task Frobenius sum-of-squares
// ---------------------------------------------------------------------------
__global__ void k_sumsq(const float* __restrict__ Aq, const float* __restrict__ Bq,
                        const float* __restrict__ Av, const float* __restrict__ Bv) {
    int b = blockIdx.x;
    const float* base;
    switch (b / NUM_T) {
        case 0:  base = Aq; break;
        case 1:  base = Bq; break;
        case 2:  base = Av; break;
        default: base = Bv; break;
    }
    base += (b % NUM_T) * SEG;
    float s = 0.f;
    for (int i = threadIdx.x; i < SEG; i += blockDim.x) {
        float v = base[i];
        s += v * v;
    }
    __shared__ float red[256];
    red[threadIdx.x] = s;
    __syncthreads();
    for (int o = 128; o > 0; o >>= 1) {
        if (threadIdx.x < o) red[threadIdx.x] += red[threadIdx.x + o];
        __syncthreads();
    }
    if (threadIdx.x == 0) g_sumsq[b] = red[0];
}

// ---------------------------------------------------------------------------
// Kernel 2: softmax gate + fold alpha / norms into per-task weights
// ---------------------------------------------------------------------------
__global__ void k_weights(const float* __restrict__ logits,
                          const float* __restrict__ alpha) {
    if (threadIdx.x == 0 && blockIdx.x == 0) {
        float mx = -1e30f;
        for (int t = 0; t < NUM_T; t++) mx = fmaxf(mx, logits[t]);
        float e[NUM_T], se = 0.f;
        for (int t = 0; t < NUM_T; t++) { e[t] = expf(logits[t] - mx); se += e[t]; }
        for (int t = 0; t < NUM_T; t++) {
            float coef = (e[t] / se) * alpha[t];
            g_wq[t] = coef / (sqrtf(g_sumsq[t])      * sqrtf(g_sumsq[10 + t]) + 1e-8f);
            g_wv[t] = coef / (sqrtf(g_sumsq[20 + t]) * sqrtf(g_sumsq[30 + t]) + 1e-8f);
        }
    }
}

// ---------------------------------------------------------------------------
// Kernel 3: build fused weight W_eff -> fp16.
// ---------------------------------------------------------------------------
__global__ __launch_bounds__(128)
void k_weff(const float* __restrict__ Aq, const float* __restrict__ Bq,
            const float* __restrict__ Av, const float* __restrict__ Bv,
            const float* __restrict__ qkvw) {
    const int d  = blockIdx.x * 128 + threadIdx.x;
    const int e0 = blockIdx.y * 16;
    const int tx = threadIdx.x;

    float acc[16];
    #pragma unroll
    for (int e = 0; e < 16; e++) acc[e] = 0.f;

    bool is_q = (e0 < DIM_D);
    bool is_v = (e0 >= 2 * DIM_D);
    if (is_q || is_v) {
        __shared__ __align__(16) float sB[NUM_T * RANK_R * 16];  // [i][e]
        const float* Am = is_q ? Aq : Av;
        const float* Bm = is_q ? Bq : Bv;
        int el0 = is_q ? e0 : (e0 - 2 * DIM_D);
        for (int idx = tx; idx < NUM_T * RANK_R * 16; idx += 128) {
            int i = idx >> 4, e = idx & 15;
            int t = i >> 4,  r = i & 15;
            float w = is_q ? g_wq[t] : g_wv[t];
            sB[idx] = w * Bm[((size_t)t * DIM_D + el0 + e) * RANK_R + r];
        }
        __syncthreads();

        const float4* sB4 = (const float4*)sB;
        #pragma unroll 32
        for (int i = 0; i < NUM_T * RANK_R; i++) {
            float a = __ldg(Am + (size_t)i * DIM_D + d);
            float4 b0 = sB4[i * 4 + 0];
            float4 b1 = sB4[i * 4 + 1];
            float4 b2 = sB4[i * 4 + 2];
            float4 b3 = sB4[i * 4 + 3];
            acc[0]  += a * b0.x;  acc[1]  += a * b0.y;
            acc[2]  += a * b0.z;  acc[3]  += a * b0.w;
            acc[4]  += a * b1.x;  acc[5]  += a * b1.y;
            acc[6]  += a * b1.z;  acc[7]  += a * b1.w;
            acc[8]  += a * b2.x;  acc[9]  += a * b2.y;
            acc[10] += a * b2.z;  acc[11] += a * b2.w;
            acc[12] += a * b3.x;  acc[13] += a * b3.y;
            acc[14] += a * b3.z;  acc[15] += a * b3.w;
        }
    }
    #pragma unroll
    for (int e = 0; e < 16; e++) {
        float val = qkvw[(size_t)(e0 + e) * DIM_D + d] + acc[e];
        g_Wh[(size_t)(e0 + e) * DIM_D + d] = __half_as_ushort(__float2half(val));
    }
}

// ---------------------------------------------------------------------------
// Kernel 3b: quantize X to fp16
// ---------------------------------------------------------------------------
__global__ void k_convert_x(const float* __restrict__ x) {
    size_t i = ((size_t)blockIdx.x * blockDim.x + threadIdx.x) * 4;
    float4 v = *(const float4*)(x + i);
    __half h0 = __float2half(v.x), h1 = __float2half(v.y),
           h2 = __float2half(v.z), h3 = __float2half(v.w);
    uint2 hh = make_uint2((uint32_t)__half_as_ushort(h0) | ((uint32_t)__half_as_ushort(h1) << 16),
                          (uint32_t)__half_as_ushort(h2) | ((uint32_t)__half_as_ushort(h3) << 16));
    *(uint2*)(g_Xh + i) = hh;
}

// ---------------------------------------------------------------------------
// Kernel 4: HMMA GEMM  out = Xh @ Wh^T + bias
//   CTA 128x256, 8 warps (2M x 4N), warp tile 64x64, BK=32, 4-stage cp.async.
// ---------------------------------------------------------------------------
__global__ __launch_bounds__(256, 1)
void k_gemm_mma(const float* __restrict__ bias, float* __restrict__ out) {
    extern __shared__ __align__(128) char smem[];
    const uint32_t sb = smem_u32(smem);
    const int tid = threadIdx.x;
    const int lid = tid & 31;
    const int wid = tid >> 5;
    const int wm = wid >> 2;         // 2 warps in M, 64 rows each
    const int wn = wid & 3;          // 4 warps in N, 64 cols each
    const int m0 = blockIdx.y * BM;
    const int n0 = blockIdx.x * BN;

    float acc[4][8][4];
    #pragma unroll
    for (int i = 0; i < 4; i++)
        #pragma unroll
        for (int j = 0; j < 8; j++)
            #pragma unroll
            for (int q = 0; q < 4; q++) acc[i][j][q] = 0.f;

    // per-lane ldmatrix offsets (80B-padded rows -> conflict-free)
    const uint32_t a_off = (uint32_t)(lid & 15) * ROWB + (uint32_t)(lid >> 4) * 16;
    const int b_nloc = (lid < 16) ? (lid & 7) : 8 + (lid & 7);
    const uint32_t b_off = (uint32_t)b_nloc * ROWB + (uint32_t)((lid >> 3) & 1) * 16;

    // stage loader: 6 cp.async of 16B per thread (A: 512 chunks, B: 1024 chunks)
    auto load_stage = [&](int s) {
        uint32_t buf = sb + (uint32_t)(s % NSTAGE) * STAGEB;
        int k0 = s * BK;
        #pragma unroll
        for (int i = 0; i < 6; i++) {
            int v = tid + i * 256;
            if (v < 512) {
                int r = v >> 2, c = v & 3;
                CP16(buf + (uint32_t)r * ROWB + (uint32_t)c * 16,
                     g_Xh + (size_t)(m0 + r) * DIM_D + k0 + c * 8);
            } else {
                int idx = v - 512;
                int r = idx >> 2, c = idx & 3;
                CP16(buf + A_BYTES + (uint32_t)r * ROWB + (uint32_t)c * 16,
                     g_Wh + (size_t)(n0 + r) * DIM_D + k0 + c * 8);
            }
        }
    };

    load_stage(0); CP_COMMIT();
    load_stage(1); CP_COMMIT();
    load_stage(2); CP_COMMIT();

    for (int s = 0; s < KSTAGES; s++) {
        CP_WAIT2();
        __syncthreads();
        if (s + 3 < KSTAGES) load_stage(s + 3);
        CP_COMMIT();

        uint32_t buf = sb + (uint32_t)(s % NSTAGE) * STAGEB;
        #pragma unroll
        for (int kk = 0; kk < 2; kk++) {
            uint32_t koff = (uint32_t)kk * 32;
            uint32_t ra[4][4], rb[4][4];
            #pragma unroll
            for (int mt = 0; mt < 4; mt++)
                ldsm_x4(ra[mt], buf + (uint32_t)(wm * 64 + mt * 16) * ROWB + koff + a_off);
            #pragma unroll
            for (int g = 0; g < 4; g++)
                ldsm_x4(rb[g], buf + A_BYTES +
                    (uint32_t)(wn * 64 + g * 16) * ROWB + koff + b_off);
            #pragma unroll
            for (int nt = 0; nt < 8; nt++) {
                uint32_t b0 = rb[nt >> 1][(nt & 1) * 2];
                uint32_t b1 = rb[nt >> 1][(nt & 1) * 2 + 1];
                #pragma unroll
                for (int mt = 0; mt < 4; mt++)
                    mma_fp16(acc[mt][nt], ra[mt], b0, b1);
            }
        }
    }

    // Epilogue: bias add + float2 stores
    const int r0 = m0 + wm * 64 + (lid >> 2);
    const int cb = n0 + wn * 64 + (lid & 3) * 2;
    #pragma unroll
    for (int nt = 0; nt < 8; nt++) {
        float2 bv = *(const float2*)(bias + cb + nt * 8);
        #pragma unroll
        for (int mt = 0; mt < 4; mt++) {
            int r = r0 + mt * 16;
            float2 v0 = make_float2(acc[mt][nt][0] + bv.x, acc[mt][nt][1] + bv.y);
            float2 v1 = make_float2(acc[mt][nt][2] + bv.x, acc[mt][nt][3] + bv.y);
            *(float2*)(out + (size_t)r * DIM_N + cb + nt * 8) = v0;
            *(float2*)(out + (size_t)(r + 8) * DIM_N + cb + nt * 8) = v1;
        }
    }
}

// ---------------------------------------------------------------------------
// Launch
// ---------------------------------------------------------------------------
extern "C" void kernel_launch(void* const* d_in, const int* in_sizes, int n_in,
                              void* d_out, int out_size) {
    const float* x      = (const float*)d_in[0];
    const float* Aq     = (const float*)d_in[1];
    const float* Bq     = (const float*)d_in[2];
    const float* Av     = (const float*)d_in[3];
    const float* Bv     = (const float*)d_in[4];
    const float* qkvw   = (const float*)d_in[5];
    const float* qkvb   = (const float*)d_in[6];
    const float* logits = (const float*)d_in[7];
    const float* alpha  = (const float*)d_in[8];
    float* out = (float*)d_out;

    cudaFuncSetAttribute(k_gemm_mma, cudaFuncAttributeMaxDynamicSharedMemorySize, SMEM_TOTAL);

    k_sumsq    <<<40, 256>>>(Aq, Bq, Av, Bv);
    k_weights  <<<1, 32>>>(logits, alpha);
    k_convert_x<<<(BATCH_M * DIM_D / 4) / 256, 256>>>(x);
    k_weff     <<<dim3(DIM_D / 128, DIM_N / 16), 128>>>(Aq, Bq, Av, Bv, qkvw);
    k_gemm_mma <<<dim3(DIM_N / BN, BATCH_M / BM), 256, SMEM_TOTAL>>>(qkvb, out);
}

// round 7
// speedup vs baseline: 1.0394x; 1.0394x over previous
#include <cuda_runtime.h>
#include <cuda_fp16.h>
#include <math.h>
#include <stdint.h>

// Problem constants
#define BATCH_M   16384   // B*S
#define DIM_D     768
#define DIM_N     2304    // 3*D
#define NUM_T     10
#define RANK_R    16
#define SEG       (RANK_R * DIM_D)

// GEMM tiling: CTA 128x128, 8 warps (4M x 2N), warp tile 32x64
#define BM 128
#define BN 128
#define BK 48                      // fp16 elems per K stage
#define KSTAGES (DIM_D / BK)       // 16

// SMEM: rows padded to 112B (conflict-free ldmatrix: 112/4=28 mod 32)
#define ROWB     112
#define ARRB     (BM * ROWB)       // 14336
#define STAGEB   (2 * ARRB)        // 28672
#define NSTAGE   4
#define SMEM_TOTAL (NSTAGE * STAGEB)   // 114688

// Device scratch (no cudaMalloc allowed)
__device__ float g_sumsq[40];
__device__ float g_wq[NUM_T];
__device__ float g_wv[NUM_T];
__device__ __align__(16) unsigned short g_Xh[(size_t)BATCH_M * DIM_D];
__device__ __align__(16) unsigned short g_Wh[(size_t)DIM_N * DIM_D];

// ---------------------------------------------------------------------------
// Helpers
// ---------------------------------------------------------------------------
__device__ __forceinline__ uint32_t smem_u32(const void* p) {
    uint32_t a;
    asm("{ .reg .u64 t; cvta.to.shared.u64 t, %1; cvt.u32.u64 %0, t; }" : "=r"(a) : "l"(p));
    return a;
}
#define CP16(dst, src) \
    asm volatile("cp.async.cg.shared.global [%0], [%1], 16;" :: "r"(dst), "l"(src))
#define CP_COMMIT() asm volatile("cp.async.commit_group;" ::: "memory")
#define CP_WAIT2()  asm volatile("cp.async.wait_group 2;"  ::: "memory")

__device__ __forceinline__ void ldsm_x4(uint32_t* r, uint32_t addr) {
    asm volatile("ldmatrix.sync.aligned.m8n8.x4.shared.b16 {%0,%1,%2,%3}, [%4];"
        : "=r"(r[0]), "=r"(r[1]), "=r"(r[2]), "=r"(r[3]) : "r"(addr));
}
__device__ __forceinline__ void mma_fp16(float* c, const uint32_t* a,
                                         uint32_t b0, uint32_t b1) {
    asm volatile("mma.sync.aligned.m16n8k16.row.col.f32.f16.f16.f32 "
        "{%0,%1,%2,%3},{%4,%5,%6,%7},{%8,%9},{%0,%1,%2,%3};"
        : "+f"(c[0]), "+f"(c[1]), "+f"(c[2]), "+f"(c[3])
        : "r"(a[0]), "r"(a[1]), "r"(a[2]), "r"(a[3]), "r"(b0), "r"(b1));
}

// ---------------------------------------------------------------------------
// Kernel 1: per-task Frobenius sum-of-squares
// ---------------------------------------------------------------------------
__global__ void k_sumsq(const float* __restrict__ Aq, const float* __restrict__ Bq,
                        const float* __restrict__ Av, const float* __restrict__ Bv) {
    int b = blockIdx.x;
    const float* base;
    switch (b / NUM_T) {
        case 0:  base = Aq; break;
        case 1:  base = Bq; break;
        case 2:  base = Av; break;
        default: base = Bv; break;
    }
    base += (b % NUM_T) * SEG;
    float s = 0.f;
    for (int i = threadIdx.x; i < SEG; i += blockDim.x) {
        float v = base[i];
        s += v * v;
    }
    __shared__ float red[256];
    red[threadIdx.x] = s;
    __syncthreads();
    for (int o = 128; o > 0; o >>= 1) {
        if (threadIdx.x < o) red[threadIdx.x] += red[threadIdx.x + o];
        __syncthreads();
    }
    if (threadIdx.x == 0) g_sumsq[b] = red[0];
}

// ---------------------------------------------------------------------------
// Kernel 2: softmax gate + fold alpha / norms into per-task weights
// ---------------------------------------------------------------------------
__global__ void k_weights(const float* __restrict__ logits,
                          const float* __restrict__ alpha) {
    if (threadIdx.x == 0 && blockIdx.x == 0) {
        float mx = -1e30f;
        for (int t = 0; t < NUM_T; t++) mx = fmaxf(mx, logits[t]);
        float e[NUM_T], se = 0.f;
        for (int t = 0; t < NUM_T; t++) { e[t] = expf(logits[t] - mx); se += e[t]; }
        for (int t = 0; t < NUM_T; t++) {
            float coef = (e[t] / se) * alpha[t];
            g_wq[t] = coef / (sqrtf(g_sumsq[t])      * sqrtf(g_sumsq[10 + t]) + 1e-8f);
            g_wv[t] = coef / (sqrtf(g_sumsq[20 + t]) * sqrtf(g_sumsq[30 + t]) + 1e-8f);
        }
    }
}

// ---------------------------------------------------------------------------
// Kernel 3: build fused weight W_eff -> fp16.
// 256 threads: 16 e-rows x 256 d-cols per block.
// ---------------------------------------------------------------------------
__global__ __launch_bounds__(256)
void k_weff(const float* __restrict__ Aq, const float* __restrict__ Bq,
            const float* __restrict__ Av, const float* __restrict__ Bv,
            const float* __restrict__ qkvw) {
    const int d  = blockIdx.x * 256 + threadIdx.x;
    const int e0 = blockIdx.y * 16;
    const int tx = threadIdx.x;

    float acc[16];
    #pragma unroll
    for (int e = 0; e < 16; e++) acc[e] = 0.f;

    bool is_q = (e0 < DIM_D);
    bool is_v = (e0 >= 2 * DIM_D);
    if (is_q || is_v) {
        __shared__ __align__(16) float sB[NUM_T * RANK_R * 16];  // [i][e]
        const float* Am = is_q ? Aq : Av;
        const float* Bm = is_q ? Bq : Bv;
        int el0 = is_q ? e0 : (e0 - 2 * DIM_D);
        for (int idx = tx; idx < NUM_T * RANK_R * 16; idx += 256) {
            int i = idx >> 4, e = idx & 15;
            int t = i >> 4,  r = i & 15;
            float w = is_q ? g_wq[t] : g_wv[t];
            sB[idx] = w * Bm[((size_t)t * DIM_D + el0 + e) * RANK_R + r];
        }
        __syncthreads();

        const float4* sB4 = (const float4*)sB;
        #pragma unroll 32
        for (int i = 0; i < NUM_T * RANK_R; i++) {
            float a = __ldg(Am + (size_t)i * DIM_D + d);
            float4 b0 = sB4[i * 4 + 0];
            float4 b1 = sB4[i * 4 + 1];
            float4 b2 = sB4[i * 4 + 2];
            float4 b3 = sB4[i * 4 + 3];
            acc[0]  += a * b0.x;  acc[1]  += a * b0.y;
            acc[2]  += a * b0.z;  acc[3]  += a * b0.w;
            acc[4]  += a * b1.x;  acc[5]  += a * b1.y;
            acc[6]  += a * b1.z;  acc[7]  += a * b1.w;
            acc[8]  += a * b2.x;  acc[9]  += a * b2.y;
            acc[10] += a * b2.z;  acc[11] += a * b2.w;
            acc[12] += a * b3.x;  acc[13] += a * b3.y;
            acc[14] += a * b3.z;  acc[15] += a * b3.w;
        }
    }
    #pragma unroll
    for (int e = 0; e < 16; e++) {
        float val = qkvw[(size_t)(e0 + e) * DIM_D + d] + acc[e];
        g_Wh[(size_t)(e0 + e) * DIM_D + d] = __half_as_ushort(__float2half(val));
    }
}

// ---------------------------------------------------------------------------
// Kernel 3b: quantize X to fp16
// ---------------------------------------------------------------------------
__global__ void k_convert_x(const float* __restrict__ x) {
    size_t i = ((size_t)blockIdx.x * blockDim.x + threadIdx.x) * 4;
    float4 v = *(const float4*)(x + i);
    __half h0 = __float2half(v.x), h1 = __float2half(v.y),
           h2 = __float2half(v.z), h3 = __float2half(v.w);
    uint2 hh = make_uint2((uint32_t)__half_as_ushort(h0) | ((uint32_t)__half_as_ushort(h1) << 16),
                          (uint32_t)__half_as_ushort(h2) | ((uint32_t)__half_as_ushort(h3) << 16));
    *(uint2*)(g_Xh + i) = hh;
}

// ---------------------------------------------------------------------------
// Kernel 4: HMMA GEMM  out = Xh @ Wh^T + bias
//   CTA 128x128, 8 warps (4M x 2N), warp tile 32x64, BK=48, 4-stage cp.async,
//   2 CTAs/SM (16 warps). One sync + one wait per stage (16 stages).
// ---------------------------------------------------------------------------
__global__ __launch_bounds__(256, 2)
void k_gemm_mma(const float* __restrict__ bias, float* __restrict__ out) {
    extern __shared__ __align__(128) char smem[];
    const uint32_t sb = smem_u32(smem);
    const int tid = threadIdx.x;
    const int lid = tid & 31;
    const int wid = tid >> 5;
    const int wm = wid & 3;          // 4 warps in M, 32 rows each
    const int wn = wid >> 2;         // 2 warps in N, 64 cols each
    const int m0 = blockIdx.y * BM;
    const int n0 = blockIdx.x * BN;

    float acc[2][8][4];
    #pragma unroll
    for (int i = 0; i < 2; i++)
        #pragma unroll
        for (int j = 0; j < 8; j++)
            #pragma unroll
            for (int q = 0; q < 4; q++) acc[i][j][q] = 0.f;

    // per-lane ldmatrix offsets (112B-padded rows -> conflict-free)
    const uint32_t a_off = (uint32_t)(lid & 15) * ROWB + (uint32_t)(lid >> 4) * 16;
    const int b_nloc = (lid < 16) ? (lid & 7) : 8 + (lid & 7);
    const uint32_t b_off = (uint32_t)b_nloc * ROWB + (uint32_t)((lid >> 3) & 1) * 16;

    // stage loader: 6 cp.async of 16B per thread (A: 768 chunks, B: 768 chunks)
    auto load_stage = [&](int s) {
        uint32_t buf = sb + (uint32_t)(s % NSTAGE) * STAGEB;
        int k0 = s * BK;
        #pragma unroll
        for (int i = 0; i < 3; i++) {           // A
            int v = tid + i * 256;              // 0..767
            int r = v / 6, c = v % 6;
            CP16(buf + (uint32_t)r * ROWB + (uint32_t)c * 16,
                 g_Xh + (size_t)(m0 + r) * DIM_D + k0 + c * 8);
        }
        #pragma unroll
        for (int i = 0; i < 3; i++) {           // B
            int v = tid + i * 256;
            int r = v / 6, c = v % 6;
            CP16(buf + ARRB + (uint32_t)r * ROWB + (uint32_t)c * 16,
                 g_Wh + (size_t)(n0 + r) * DIM_D + k0 + c * 8);
        }
    };

    load_stage(0); CP_COMMIT();
    load_stage(1); CP_COMMIT();
    load_stage(2); CP_COMMIT();

    for (int s = 0; s < KSTAGES; s++) {
        CP_WAIT2();                  // stage s resident
        __syncthreads();             // all warps done with stage s-1 (buf (s+3)%4)
        if (s + 3 < KSTAGES) load_stage(s + 3);
        CP_COMMIT();

        uint32_t buf = sb + (uint32_t)(s % NSTAGE) * STAGEB;
        #pragma unroll
        for (int kk = 0; kk < 3; kk++) {
            uint32_t koff = (uint32_t)kk * 32;
            uint32_t ra[2][4];
            #pragma unroll
            for (int mt = 0; mt < 2; mt++)
                ldsm_x4(ra[mt], buf + (uint32_t)(wm * 32 + mt * 16) * ROWB + koff + a_off);
            #pragma unroll
            for (int half = 0; half < 2; half++) {
                uint32_t rb[2][4];
                #pragma unroll
                for (int g = 0; g < 2; g++)
                    ldsm_x4(rb[g], buf + ARRB +
                        (uint32_t)(wn * 64 + (half * 2 + g) * 16) * ROWB + koff + b_off);
                #pragma unroll
                for (int mt = 0; mt < 2; mt++)
                    #pragma unroll
                    for (int n4 = 0; n4 < 4; n4++) {
                        uint32_t b0 = rb[n4 >> 1][(n4 & 1) * 2];
                        uint32_t b1 = rb[n4 >> 1][(n4 & 1) * 2 + 1];
                        mma_fp16(acc[mt][half * 4 + n4], ra[mt], b0, b1);
                    }
            }
        }
    }

    // Epilogue: bias add + float2 stores
    const int r0 = m0 + wm * 32 + (lid >> 2);
    const int cb = n0 + wn * 64 + (lid & 3) * 2;
    #pragma unroll
    for (int nt = 0; nt < 8; nt++) {
        float2 bv = *(const float2*)(bias + cb + nt * 8);
        #pragma unroll
        for (int mt = 0; mt < 2; mt++) {
            int r = r0 + mt * 16;
            float2 v0 = make_float2(acc[mt][nt][0] + bv.x, acc[mt][nt][1] + bv.y);
            float2 v1 = make_float2(acc[mt][nt][2] + bv.x, acc[mt][nt][3] + bv.y);
            *(float2*)(out + (size_t)r * DIM_N + cb + nt * 8) = v0;
            *(float2*)(out + (size_t)(r + 8) * DIM_N + cb + nt * 8) = v1;
        }
    }
}

// ---------------------------------------------------------------------------
// Launch
// ---------------------------------------------------------------------------
extern "C" void kernel_launch(void* const* d_in, const int* in_sizes, int n_in,
                              void* d_out, int out_size) {
    const float* x      = (const float*)d_in[0];
    const float* Aq     = (const float*)d_in[1];
    const float* Bq     = (const float*)d_in[2];
    const float* Av     = (const float*)d_in[3];
    const float* Bv     = (const float*)d_in[4];
    const float* qkvw   = (const float*)d_in[5];
    const float* qkvb   = (const float*)d_in[6];
    const float* logits = (const float*)d_in[7];
    const float* alpha  = (const float*)d_in[8];
    float* out = (float*)d_out;

    cudaFuncSetAttribute(k_gemm_mma, cudaFuncAttributeMaxDynamicSharedMemorySize, SMEM_TOTAL);

    k_sumsq    <<<40, 256>>>(Aq, Bq, Av, Bv);
    k_weights  <<<1, 32>>>(logits, alpha);
    k_convert_x<<<(BATCH_M * DIM_D / 4) / 256, 256>>>(x);
    k_weff     <<<dim3(DIM_D / 256, DIM_N / 16), 256>>>(Aq, Bq, Av, Bv, qkvw);
    k_gemm_mma <<<dim3(DIM_N / BN, BATCH_M / BM), 256, SMEM_TOTAL>>>(qkvb, out);
}